// round 2
// baseline (speedup 1.0000x reference)
#include <cuda_runtime.h>

#define N_NODES 100000
#define N_PAIRS 160000
#define N_EDGES 320000
#define HIDDEN  256
#define DEPTH   3

// ---------------- scratch (device globals; no runtime allocation) ----------------
__device__ float g_H[(size_t)N_EDGES * HIDDEN];      // ping buffer for H
__device__ float g_Mv[(size_t)N_NODES * HIDDEN];     // per-layer node sums
__device__ int   g_counts[N_NODES];
__device__ int   g_offs[N_NODES + 1];
__device__ int   g_cursor[N_NODES];
__device__ int   g_elist[N_EDGES];

// ---------------- small utility kernels ----------------
__global__ void k_zero_counts() {
    int i = blockIdx.x * blockDim.x + threadIdx.x;
    if (i < N_NODES) g_counts[i] = 0;
}

__global__ void k_hist(const int* __restrict__ src) {
    int e = blockIdx.x * blockDim.x + threadIdx.x;
    if (e < N_EDGES) atomicAdd(&g_counts[src[e]], 1);
}

// single-block exclusive scan over g_counts -> g_offs (N_NODES+1) and g_cursor
__global__ void k_scan() {
    __shared__ int s_carry;
    __shared__ int s_wsum[32];
    if (threadIdx.x == 0) s_carry = 0;
    __syncthreads();
    for (int base = 0; base < N_NODES; base += 1024) {
        int i = base + (int)threadIdx.x;
        int v = (i < N_NODES) ? g_counts[i] : 0;
        int lane = threadIdx.x & 31, w = threadIdx.x >> 5;
        int sc = v;
        #pragma unroll
        for (int d = 1; d < 32; d <<= 1) {
            int t = __shfl_up_sync(0xffffffffu, sc, d);
            if (lane >= d) sc += t;
        }
        if (lane == 31) s_wsum[w] = sc;
        __syncthreads();
        if (w == 0) {
            int ws = s_wsum[lane];
            #pragma unroll
            for (int d = 1; d < 32; d <<= 1) {
                int t = __shfl_up_sync(0xffffffffu, ws, d);
                if (lane >= d) ws += t;
            }
            s_wsum[lane] = ws;
        }
        __syncthreads();
        int incl = sc + (w > 0 ? s_wsum[w - 1] : 0) + s_carry;
        if (i < N_NODES) {
            g_offs[i] = incl - v;
            g_cursor[i] = incl - v;
        }
        __syncthreads();
        if (threadIdx.x == 1023) s_carry = incl;
        __syncthreads();
    }
    if (threadIdx.x == 0) g_offs[N_NODES] = s_carry;
}

__global__ void k_fill(const int* __restrict__ src) {
    int e = blockIdx.x * blockDim.x + threadIdx.x;
    if (e < N_EDGES) {
        int pos = atomicAdd(&g_cursor[src[e]], 1);
        g_elist[pos] = e;
    }
}

// H0[e] = V[src[e]] + E[e]
__global__ void k_init(const float* __restrict__ V, const float* __restrict__ E,
                       const int* __restrict__ src, float* __restrict__ H) {
    int i = blockIdx.x * blockDim.x + threadIdx.x;
    if (i >= N_EDGES * (HIDDEN / 4)) return;
    int e = i >> 6;
    int c = i & 63;
    int s = src[e];
    float4 ev = ((const float4*)E)[(size_t)e * 64 + c];
    float4 vv = ((const float4*)V)[(size_t)s * 64 + c];
    float4 o;
    o.x = ev.x + vv.x; o.y = ev.y + vv.y; o.z = ev.z + vv.z; o.w = ev.w + vv.w;
    ((float4*)H)[(size_t)e * 64 + c] = o;
}

// Segment sum over nodes via CSR (src-list). 4 nodes per block (y dim).
// RELU_REV=true: Mv[n] = sum relu(H[rev[e]]) (== segment_sum over dest).
// RELU_REV=false: out[n] = sum H[e] (final V_out).
template <bool RELU_REV>
__global__ void k_segsum(const float* __restrict__ H, const int* __restrict__ rev,
                         float* __restrict__ out) {
    int n = blockIdx.x * 4 + threadIdx.y;
    if (n >= N_NODES) return;
    int c = threadIdx.x;  // 0..63 -> float4 column
    int beg = g_offs[n], end = g_offs[n + 1];
    float4 acc = make_float4(0.f, 0.f, 0.f, 0.f);
    for (int p = beg; p < end; ++p) {
        int e = g_elist[p];
        if (RELU_REV) e = rev[e];
        float4 h = *(const float4*)(H + (size_t)e * HIDDEN + c * 4);
        if (RELU_REV) {
            h.x = fmaxf(h.x, 0.f); h.y = fmaxf(h.y, 0.f);
            h.z = fmaxf(h.z, 0.f); h.w = fmaxf(h.w, 0.f);
        }
        acc.x += h.x; acc.y += h.y; acc.z += h.z; acc.w += h.w;
    }
    *(float4*)(out + (size_t)n * HIDDEN + c * 4) = acc;
}

// ---------------- fused tf32 GEMM ----------------
// H_out[e,:] = H_in[e,:] + (Mv[src[e],:] - relu(H_in[rev[e],:])) @ W^T + b
// M = N_EDGES, N = 256, K = 256. Block tile 64x256, BK=16, 8 warps (2x4), warp 32x64.
// Smem uses "pair-packed" k layout: within each 8-k group, element k stored at
// slot (k&3)*2 + (k>>2 & 1), so each mma fragment (k, k+4) is one float2 load.

#define BM 64
#define BN 256
#define BK 16
#define RS 18   // floats per packed row (16 slots + 2 pad)
#define GEMM_SMEM (2 * (BM + BN) * RS * 4)

__device__ __forceinline__ float f_tf32(float x) {
    float y;
    asm("cvt.rna.tf32.f32 %0, %1;" : "=f"(y) : "f"(x));
    return y;
}

__device__ __forceinline__ void mma_tf32(float* d, const unsigned* a, const unsigned* b) {
    asm volatile(
        "mma.sync.aligned.m16n8k8.row.col.f32.tf32.tf32.f32 "
        "{%0,%1,%2,%3}, {%4,%5,%6,%7}, {%8,%9}, {%0,%1,%2,%3};\n"
        : "+f"(d[0]), "+f"(d[1]), "+f"(d[2]), "+f"(d[3])
        : "r"(a[0]), "r"(a[1]), "r"(a[2]), "r"(a[3]), "r"(b[0]), "r"(b[1]));
}

__global__ void __launch_bounds__(256)
k_gemm(const float* __restrict__ Hin, const float* __restrict__ Mv,
       const int* __restrict__ src, const int* __restrict__ rev,
       const float* __restrict__ Wl, const float* __restrict__ bl,
       float* __restrict__ Hout) {
    extern __shared__ float sm[];
    float* sA = sm;                    // [2][BM][RS]
    float* sB = sm + 2 * BM * RS;      // [2][BN][RS]
    __shared__ int s_src[BM], s_rev[BM];

    const int t = threadIdx.x;
    const int rowbase = blockIdx.x * BM;
    if (t < BM) {
        int e = rowbase + t;
        s_src[t] = src[e];
        s_rev[t] = rev[e];
    }
    __syncthreads();

    const int lane = t & 31, wid = t >> 5;
    const int wm = wid >> 2, wn = wid & 3;
    const int lr = lane >> 2, lc = lane & 3;

    float acc[2][8][4];
    #pragma unroll
    for (int mi = 0; mi < 2; ++mi)
        #pragma unroll
        for (int ni = 0; ni < 8; ++ni)
            #pragma unroll
            for (int j = 0; j < 4; ++j) acc[mi][ni][j] = 0.f;

    // staging registers
    float4 ra;
    float4 rb[4];
    const int arow = t >> 2;
    const int ac4 = (t & 3) * 4;
    const int a_g = ac4 >> 3;              // k8-group of this thread's 4 elements
    const int a_hi = (ac4 >> 2) & 1;       // which half (k or k+4)
    const int a_slot = a_g * 8 + a_hi;

    auto ldTile = [&](int kt) {
        int k0 = kt * BK;
        {
            int s = s_src[arow], r = s_rev[arow];
            float4 m = *(const float4*)(Mv + (size_t)s * HIDDEN + k0 + ac4);
            float4 h = *(const float4*)(Hin + (size_t)r * HIDDEN + k0 + ac4);
            ra.x = m.x - fmaxf(h.x, 0.f);
            ra.y = m.y - fmaxf(h.y, 0.f);
            ra.z = m.z - fmaxf(h.z, 0.f);
            ra.w = m.w - fmaxf(h.w, 0.f);
        }
        #pragma unroll
        for (int i = 0; i < 4; ++i) {
            int f = t + i * 256;
            int n = f >> 2;
            int c = (f & 3) * 4;
            rb[i] = *(const float4*)(Wl + (size_t)n * HIDDEN + k0 + c);
        }
    };

    auto stTile = [&](int buf) {
        float* pa = sA + buf * BM * RS + arow * RS + a_slot;
        pa[0] = f_tf32(ra.x); pa[2] = f_tf32(ra.y);
        pa[4] = f_tf32(ra.z); pa[6] = f_tf32(ra.w);
        #pragma unroll
        for (int i = 0; i < 4; ++i) {
            int f = t + i * 256;
            int n = f >> 2;
            int c = (f & 3) * 4;
            int slot = (c >> 3) * 8 + ((c >> 2) & 1);
            float* pb = sB + buf * BN * RS + n * RS + slot;
            pb[0] = f_tf32(rb[i].x); pb[2] = f_tf32(rb[i].y);
            pb[4] = f_tf32(rb[i].z); pb[6] = f_tf32(rb[i].w);
        }
    };

    auto compute = [&](int buf) {
        const float* A0 = sA + buf * BM * RS + (wm * 32) * RS;
        const float* B0 = sB + buf * BN * RS + (wn * 64) * RS;
        #pragma unroll
        for (int g = 0; g < 2; ++g) {
            const int slot = g * 8 + lc * 2;
            unsigned af[2][4], bf[8][2];
            #pragma unroll
            for (int mi = 0; mi < 2; ++mi) {
                const float* a = A0 + (mi * 16 + lr) * RS + slot;
                float2 lo = *(const float2*)a;
                float2 hi = *(const float2*)(a + 8 * RS);
                af[mi][0] = __float_as_uint(lo.x);
                af[mi][1] = __float_as_uint(hi.x);
                af[mi][2] = __float_as_uint(lo.y);
                af[mi][3] = __float_as_uint(hi.y);
            }
            #pragma unroll
            for (int ni = 0; ni < 8; ++ni) {
                float2 bb = *(const float2*)(B0 + (ni * 8 + lr) * RS + slot);
                bf[ni][0] = __float_as_uint(bb.x);
                bf[ni][1] = __float_as_uint(bb.y);
            }
            #pragma unroll
            for (int mi = 0; mi < 2; ++mi)
                #pragma unroll
                for (int ni = 0; ni < 8; ++ni)
                    mma_tf32(acc[mi][ni], af[mi], bf[ni]);
        }
    };

    ldTile(0);
    stTile(0);
    __syncthreads();

    const int KT = HIDDEN / BK;  // 16
    for (int kt = 0; kt < KT; ++kt) {
        int buf = kt & 1;
        if (kt < KT - 1) ldTile(kt + 1);
        compute(buf);
        if (kt < KT - 1) stTile(buf ^ 1);
        __syncthreads();
    }

    // epilogue: H_out = H_in + acc + b   (bias hoisted to registers)
    float2 bb[8];
    #pragma unroll
    for (int ni = 0; ni < 8; ++ni)
        bb[ni] = *(const float2*)(bl + wn * 64 + ni * 8 + lc * 2);

    #pragma unroll
    for (int mi = 0; mi < 2; ++mi) {
        #pragma unroll
        for (int ni = 0; ni < 8; ++ni) {
            int r0 = rowbase + wm * 32 + mi * 16 + lr;
            int c0 = wn * 64 + ni * 8 + lc * 2;
            {
                float2 h = *(const float2*)(Hin + (size_t)r0 * HIDDEN + c0);
                float2 o;
                o.x = h.x + bb[ni].x + acc[mi][ni][0];
                o.y = h.y + bb[ni].y + acc[mi][ni][1];
                *(float2*)(Hout + (size_t)r0 * HIDDEN + c0) = o;
            }
            {
                int r1 = r0 + 8;
                float2 h = *(const float2*)(Hin + (size_t)r1 * HIDDEN + c0);
                float2 o;
                o.x = h.x + bb[ni].x + acc[mi][ni][2];
                o.y = h.y + bb[ni].y + acc[mi][ni][3];
                *(float2*)(Hout + (size_t)r1 * HIDDEN + c0) = o;
            }
        }
    }
}

// ---------------- launch ----------------
extern "C" void kernel_launch(void* const* d_in, const int* in_sizes, int n_in,
                              void* d_out, int out_size) {
    const float* V = (const float*)d_in[0];
    const float* E = (const float*)d_in[1];
    const float* W = (const float*)d_in[2];
    const float* b = (const float*)d_in[3];
    const int* edge_index = (const int*)d_in[4];
    const int* rev = (const int*)d_in[5];
    const int* src = edge_index;  // first N_EDGES entries

    float* outV = (float*)d_out;
    float* outH = outV + (size_t)N_NODES * HIDDEN;

    float* gH = nullptr;
    float* gMv = nullptr;
    cudaGetSymbolAddress((void**)&gH, g_H);
    cudaGetSymbolAddress((void**)&gMv, g_Mv);

    cudaFuncSetAttribute(k_gemm, cudaFuncAttributeMaxDynamicSharedMemorySize, GEMM_SMEM);

    const int nb_nodes = (N_NODES + 255) / 256;
    const int nb_edges = (N_EDGES + 255) / 256;

    // H0 = V[src] + E (independent of CSR build; launched first)
    k_init<<<(N_EDGES * 64 + 255) / 256, 256>>>(V, E, src, gH);

    // build CSR by src (also serves dest via rev)
    k_zero_counts<<<nb_nodes, 256>>>();
    k_hist<<<nb_edges, 256>>>(src);
    k_scan<<<1, 1024>>>();
    k_fill<<<nb_edges, 256>>>(src);

    // layer ping-pong: gH -> outH -> gH -> outH
    dim3 segBlk(64, 4);
    float* bufs[2] = {gH, outH};
    for (int l = 0; l < DEPTH; ++l) {
        const float* Hin = bufs[l & 1];
        float* Hout = bufs[(l + 1) & 1];
        k_segsum<true><<<(N_NODES + 3) / 4, segBlk>>>(Hin, rev, gMv);
        k_gemm<<<N_EDGES / BM, 256, GEMM_SMEM>>>(Hin, gMv, src, rev,
                                                 W + (size_t)l * HIDDEN * HIDDEN,
                                                 b + (size_t)l * HIDDEN, Hout);
    }

    // V_out = segment_sum(H, src) ; H already in outH
    k_segsum<false><<<(N_NODES + 3) / 4, segBlk>>>(outH, rev, outV);
}

// round 3
// speedup vs baseline: 1.3361x; 1.3361x over previous
#include <cuda_runtime.h>

#define N_NODES 100000
#define N_PAIRS 160000
#define N_EDGES 320000
#define HIDDEN  256
#define DEPTH   3

// ---------------- scratch (device globals; no runtime allocation) ----------------
__device__ float g_H[(size_t)N_EDGES * HIDDEN];      // ping buffer for H
__device__ float g_Mv[(size_t)N_NODES * HIDDEN];     // per-layer node sums
__device__ float g_Wt[(size_t)DEPTH * HIDDEN * HIDDEN]; // tf32-preconverted W
__device__ int   g_counts[N_NODES];
__device__ int   g_offs[N_NODES + 1];
__device__ int   g_cursor[N_NODES];
__device__ int   g_elist[N_EDGES];
__device__ int   g_bsums[128];
__device__ int   g_bpre[128];

__device__ __forceinline__ float f_tf32(float x) {
    float y;
    asm("cvt.rna.tf32.f32 %0, %1;" : "=f"(y) : "f"(x));
    return y;
}

// ---------------- small utility kernels ----------------
__global__ void k_zero_counts() {
    int i = blockIdx.x * blockDim.x + threadIdx.x;
    if (i < N_NODES) g_counts[i] = 0;
}

__global__ void k_hist(const int* __restrict__ src) {
    int e = blockIdx.x * blockDim.x + threadIdx.x;
    if (e < N_EDGES) atomicAdd(&g_counts[src[e]], 1);
}

// W -> tf32 preconvert (vectorized)
__global__ void k_cvtW(const float* __restrict__ W) {
    int i = blockIdx.x * blockDim.x + threadIdx.x;
    if (i >= DEPTH * HIDDEN * HIDDEN / 4) return;
    float4 w = ((const float4*)W)[i];
    float4 o;
    o.x = f_tf32(w.x); o.y = f_tf32(w.y); o.z = f_tf32(w.z); o.w = f_tf32(w.w);
    ((float4*)g_Wt)[i] = o;
}

// ---- hierarchical scan: phase 1 (per-block exclusive scan + block sums) ----
__global__ void k_scan1() {
    __shared__ int s_wsum[32];
    int b = blockIdx.x;
    int i = b * 1024 + threadIdx.x;
    int v = (i < N_NODES) ? g_counts[i] : 0;
    int lane = threadIdx.x & 31, w = threadIdx.x >> 5;
    int sc = v;
    #pragma unroll
    for (int d = 1; d < 32; d <<= 1) {
        int t = __shfl_up_sync(0xffffffffu, sc, d);
        if (lane >= d) sc += t;
    }
    if (lane == 31) s_wsum[w] = sc;
    __syncthreads();
    if (w == 0) {
        int ws = s_wsum[lane];
        #pragma unroll
        for (int d = 1; d < 32; d <<= 1) {
            int t = __shfl_up_sync(0xffffffffu, ws, d);
            if (lane >= d) ws += t;
        }
        s_wsum[lane] = ws;
    }
    __syncthreads();
    int excl = sc - v + (w > 0 ? s_wsum[w - 1] : 0);
    if (i < N_NODES) g_offs[i] = excl;   // local exclusive, prefix added in phase 3
    if (threadIdx.x == 1023) g_bsums[b] = s_wsum[31];
}

// ---- phase 2: single-warp scan of block sums ----
__global__ void k_scan2(int nb) {
    int lane = threadIdx.x;
    int carry = 0;
    for (int base = 0; base < nb; base += 32) {
        int i = base + lane;
        int v = (i < nb) ? g_bsums[i] : 0;
        int sc = v;
        #pragma unroll
        for (int d = 1; d < 32; d <<= 1) {
            int t = __shfl_up_sync(0xffffffffu, sc, d);
            if (lane >= d) sc += t;
        }
        if (i < nb) g_bpre[i] = carry + sc - v;
        carry += __shfl_sync(0xffffffffu, sc, 31);
    }
    if (lane == 0) g_offs[N_NODES] = carry;
}

// ---- phase 3: add block prefix, init cursor ----
__global__ void k_scan3() {
    int i = blockIdx.x * blockDim.x + threadIdx.x;
    if (i < N_NODES) {
        int o = g_offs[i] + g_bpre[i >> 10];
        g_offs[i] = o;
        g_cursor[i] = o;
    }
}

__global__ void k_fill(const int* __restrict__ src) {
    int e = blockIdx.x * blockDim.x + threadIdx.x;
    if (e < N_EDGES) {
        int pos = atomicAdd(&g_cursor[src[e]], 1);
        g_elist[pos] = e;
    }
}

// H0[e] = V[src[e]] + E[e]
__global__ void k_init(const float* __restrict__ V, const float* __restrict__ E,
                       const int* __restrict__ src, float* __restrict__ H) {
    int i = blockIdx.x * blockDim.x + threadIdx.x;
    if (i >= N_EDGES * (HIDDEN / 4)) return;
    int e = i >> 6;
    int c = i & 63;
    int s = src[e];
    float4 ev = ((const float4*)E)[(size_t)e * 64 + c];
    float4 vv = ((const float4*)V)[(size_t)s * 64 + c];
    float4 o;
    o.x = ev.x + vv.x; o.y = ev.y + vv.y; o.z = ev.z + vv.z; o.w = ev.w + vv.w;
    ((float4*)H)[(size_t)e * 64 + c] = o;
}

// Segment sum over nodes via CSR (src-list).
// RELU_REV=true: Mv[n] = sum relu(H[rev[e]]) (== segment_sum over dest).
// RELU_REV=false: out[n] = sum H[e] (final V_out).
template <bool RELU_REV>
__global__ void k_segsum(const float* __restrict__ H, const int* __restrict__ rev,
                         float* __restrict__ out) {
    int n = blockIdx.x;
    int c = threadIdx.x;  // 0..63 -> float4 column
    int beg = g_offs[n], end = g_offs[n + 1];
    float4 acc = make_float4(0.f, 0.f, 0.f, 0.f);
    for (int p = beg; p < end; ++p) {
        int e = g_elist[p];
        if (RELU_REV) e = rev[e];
        float4 h = *(const float4*)(H + (size_t)e * HIDDEN + c * 4);
        if (RELU_REV) {
            h.x = fmaxf(h.x, 0.f); h.y = fmaxf(h.y, 0.f);
            h.z = fmaxf(h.z, 0.f); h.w = fmaxf(h.w, 0.f);
        }
        acc.x += h.x; acc.y += h.y; acc.z += h.z; acc.w += h.w;
    }
    *(float4*)(out + (size_t)n * HIDDEN + c * 4) = acc;
}

// ---------------- fused tf32 GEMM, 4-stage pipeline ----------------
// H_out[e,:] = H_in[e,:] + (Mv[src[e],:] - relu(H_in[rev[e],:])) @ W^T + b
// M = N_EDGES, N = 256, K = 256. Block tile 64x256, BK=16, 8 warps (2x4), warp 32x64.
// B (pre-tf32 W) staged via cp.async (4 stages); A built in regs (2-deep queue) -> STS.

#define BM 64
#define BN 256
#define BK 16
#define PAD 20
#define STAGES 4
#define GEMM_SMEM (STAGES * (BM + BN) * PAD * 4)

__device__ __forceinline__ void mma_tf32(float* d, const unsigned* a, const unsigned* b) {
    asm volatile(
        "mma.sync.aligned.m16n8k8.row.col.f32.tf32.tf32.f32 "
        "{%0,%1,%2,%3}, {%4,%5,%6,%7}, {%8,%9}, {%0,%1,%2,%3};\n"
        : "+f"(d[0]), "+f"(d[1]), "+f"(d[2]), "+f"(d[3])
        : "r"(a[0]), "r"(a[1]), "r"(a[2]), "r"(a[3]), "r"(b[0]), "r"(b[1]));
}

__global__ void __launch_bounds__(256, 2)
k_gemm(const float* __restrict__ Hin, const float* __restrict__ Mv,
       const int* __restrict__ src, const int* __restrict__ rev,
       const float* __restrict__ Wl, const float* __restrict__ bl,
       float* __restrict__ Hout) {
    extern __shared__ float sm[];
    float* sA = sm;                          // [STAGES][BM*PAD]
    float* sB = sm + STAGES * BM * PAD;      // [STAGES][BN*PAD]
    __shared__ int s_src[BM], s_rev[BM];

    const int t = threadIdx.x;
    const int rowbase = blockIdx.x * BM;
    if (t < BM) {
        int e = rowbase + t;
        s_src[t] = src[e];
        s_rev[t] = rev[e];
    }
    __syncthreads();

    const int lane = t & 31, wid = t >> 5;
    const int wm = wid >> 2, wn = wid & 3;
    const int lr = lane >> 2, lc = lane & 3;

    float acc[2][8][4];
    #pragma unroll
    for (int mi = 0; mi < 2; ++mi)
        #pragma unroll
        for (int ni = 0; ni < 8; ++ni)
            #pragma unroll
            for (int j = 0; j < 4; ++j) acc[mi][ni][j] = 0.f;

    const int arow = t >> 2;
    const int ac4 = (t & 3) * 4;
    const float* mvbase = Mv + (size_t)s_src[arow] * HIDDEN + ac4;
    const float* hbase  = Hin + (size_t)s_rev[arow] * HIDDEN + ac4;

    float4 qm[2], qh[2];

    // issue cp.async for B stage kt
    auto issueB = [&](int kt) {
        float* sBs = sB + (kt & (STAGES - 1)) * BN * PAD;
        int k0 = kt * BK;
        #pragma unroll
        for (int i = 0; i < 4; ++i) {
            int f = t + i * 256;
            int n = f >> 2;
            int c = (f & 3) * 4;
            unsigned dst = (unsigned)__cvta_generic_to_shared(sBs + n * PAD + c);
            const float* sp = Wl + (size_t)n * HIDDEN + k0 + c;
            asm volatile("cp.async.cg.shared.global [%0], [%1], 16;\n" :: "r"(dst), "l"(sp));
        }
        asm volatile("cp.async.commit_group;\n");
    };

    auto compute = [&](int stage) {
        const float* A0 = sA + stage * BM * PAD + (wm * 32) * PAD;
        const float* B0 = sB + stage * BN * PAD + (wn * 64) * PAD;
        #pragma unroll
        for (int ks = 0; ks < 2; ++ks) {
            int k = ks * 8;
            unsigned af[2][4], bf[8][2];
            #pragma unroll
            for (int mi = 0; mi < 2; ++mi) {
                const float* a = A0 + (mi * 16 + lr) * PAD + k + lc;
                af[mi][0] = __float_as_uint(a[0]);
                af[mi][1] = __float_as_uint(a[8 * PAD]);
                af[mi][2] = __float_as_uint(a[4]);
                af[mi][3] = __float_as_uint(a[8 * PAD + 4]);
            }
            #pragma unroll
            for (int ni = 0; ni < 8; ++ni) {
                const float* bp = B0 + (ni * 8 + lr) * PAD + k + lc;
                bf[ni][0] = __float_as_uint(bp[0]);
                bf[ni][1] = __float_as_uint(bp[4]);
            }
            #pragma unroll
            for (int mi = 0; mi < 2; ++mi)
                #pragma unroll
                for (int ni = 0; ni < 8; ++ni)
                    mma_tf32(acc[mi][ni], af[mi], bf[ni]);
        }
    };

    const int KT = HIDDEN / BK;  // 16

    // prologue: B stages 0..2 in flight; A stages 0,1 stored; A kt=2,3 in regs
    issueB(0); issueB(1); issueB(2);
    qm[0] = *(const float4*)(mvbase + 0 * BK);
    qh[0] = *(const float4*)(hbase + 0 * BK);
    qm[1] = *(const float4*)(mvbase + 1 * BK);
    qh[1] = *(const float4*)(hbase + 1 * BK);
    {
        float* pa = sA + 0 * BM * PAD + arow * PAD + ac4;
        pa[0] = f_tf32(qm[0].x - fmaxf(qh[0].x, 0.f));
        pa[1] = f_tf32(qm[0].y - fmaxf(qh[0].y, 0.f));
        pa[2] = f_tf32(qm[0].z - fmaxf(qh[0].z, 0.f));
        pa[3] = f_tf32(qm[0].w - fmaxf(qh[0].w, 0.f));
    }
    qm[0] = *(const float4*)(mvbase + 2 * BK);
    qh[0] = *(const float4*)(hbase + 2 * BK);
    {
        float* pa = sA + 1 * BM * PAD + arow * PAD + ac4;
        pa[0] = f_tf32(qm[1].x - fmaxf(qh[1].x, 0.f));
        pa[1] = f_tf32(qm[1].y - fmaxf(qh[1].y, 0.f));
        pa[2] = f_tf32(qm[1].z - fmaxf(qh[1].z, 0.f));
        pa[3] = f_tf32(qm[1].w - fmaxf(qh[1].w, 0.f));
    }
    qm[1] = *(const float4*)(mvbase + 3 * BK);
    qh[1] = *(const float4*)(hbase + 3 * BK);

    #pragma unroll
    for (int kt = 0; kt < KT; ++kt) {
        // wait for B(kt); stages in flight: committed up to min(kt+2, KT-1)
        if (kt + 3 < KT)      asm volatile("cp.async.wait_group 2;\n");
        else if (kt + 2 < KT) asm volatile("cp.async.wait_group 1;\n");
        else if (kt + 1 < KT) asm volatile("cp.async.wait_group 0;\n");
        __syncthreads();

        compute(kt & (STAGES - 1));

        if (kt + 3 < KT) issueB(kt + 3);
        if (kt + 2 < KT) {
            const int s = kt & 1;
            float* pa = sA + ((kt + 2) & (STAGES - 1)) * BM * PAD + arow * PAD + ac4;
            pa[0] = f_tf32(qm[s].x - fmaxf(qh[s].x, 0.f));
            pa[1] = f_tf32(qm[s].y - fmaxf(qh[s].y, 0.f));
            pa[2] = f_tf32(qm[s].z - fmaxf(qh[s].z, 0.f));
            pa[3] = f_tf32(qm[s].w - fmaxf(qh[s].w, 0.f));
        }
        if (kt + 4 < KT) {
            const int s = kt & 1;
            qm[s] = *(const float4*)(mvbase + (kt + 4) * BK);
            qh[s] = *(const float4*)(hbase + (kt + 4) * BK);
        }
    }

    // epilogue: H_out = H_in + acc + b   (bias in registers)
    float2 bb[8];
    #pragma unroll
    for (int ni = 0; ni < 8; ++ni)
        bb[ni] = *(const float2*)(bl + wn * 64 + ni * 8 + lc * 2);

    #pragma unroll
    for (int mi = 0; mi < 2; ++mi) {
        #pragma unroll
        for (int ni = 0; ni < 8; ++ni) {
            int r0 = rowbase + wm * 32 + mi * 16 + lr;
            int c0 = wn * 64 + ni * 8 + lc * 2;
            {
                float2 h = *(const float2*)(Hin + (size_t)r0 * HIDDEN + c0);
                float2 o;
                o.x = h.x + bb[ni].x + acc[mi][ni][0];
                o.y = h.y + bb[ni].y + acc[mi][ni][1];
                *(float2*)(Hout + (size_t)r0 * HIDDEN + c0) = o;
            }
            {
                int r1 = r0 + 8;
                float2 h = *(const float2*)(Hin + (size_t)r1 * HIDDEN + c0);
                float2 o;
                o.x = h.x + bb[ni].x + acc[mi][ni][2];
                o.y = h.y + bb[ni].y + acc[mi][ni][3];
                *(float2*)(Hout + (size_t)r1 * HIDDEN + c0) = o;
            }
        }
    }
}

// ---------------- launch ----------------
extern "C" void kernel_launch(void* const* d_in, const int* in_sizes, int n_in,
                              void* d_out, int out_size) {
    const float* V = (const float*)d_in[0];
    const float* E = (const float*)d_in[1];
    const float* W = (const float*)d_in[2];
    const float* b = (const float*)d_in[3];
    const int* edge_index = (const int*)d_in[4];
    const int* rev = (const int*)d_in[5];
    const int* src = edge_index;  // first N_EDGES entries

    float* outV = (float*)d_out;
    float* outH = outV + (size_t)N_NODES * HIDDEN;

    float* gH = nullptr;
    float* gMv = nullptr;
    float* gWt = nullptr;
    cudaGetSymbolAddress((void**)&gH, g_H);
    cudaGetSymbolAddress((void**)&gMv, g_Mv);
    cudaGetSymbolAddress((void**)&gWt, g_Wt);

    cudaFuncSetAttribute(k_gemm, cudaFuncAttributeMaxDynamicSharedMemorySize, GEMM_SMEM);

    const int nb_nodes = (N_NODES + 255) / 256;
    const int nb_edges = (N_EDGES + 255) / 256;
    const int nb_scan = (N_NODES + 1023) / 1024;  // 98

    // CSR build (scan is hierarchical now)
    k_zero_counts<<<nb_nodes, 256>>>();
    k_hist<<<nb_edges, 256>>>(src);
    k_scan1<<<nb_scan, 1024>>>();
    k_scan2<<<1, 32>>>(nb_scan);
    k_scan3<<<nb_nodes, 256>>>();
    k_fill<<<nb_edges, 256>>>(src);

    // W -> tf32; H0 = V[src] + E
    k_cvtW<<<(DEPTH * HIDDEN * HIDDEN / 4 + 255) / 256, 256>>>(W);
    k_init<<<(N_EDGES * 64 + 255) / 256, 256>>>(V, E, src, gH);

    // layer ping-pong: gH -> outH -> gH -> outH
    float* bufs[2] = {gH, outH};
    for (int l = 0; l < DEPTH; ++l) {
        const float* Hin = bufs[l & 1];
        float* Hout = bufs[(l + 1) & 1];
        k_segsum<true><<<N_NODES, 64>>>(Hin, rev, gMv);
        k_gemm<<<N_EDGES / BM, 256, GEMM_SMEM>>>(Hin, gMv, src, rev,
                                                 gWt + (size_t)l * HIDDEN * HIDDEN,
                                                 b + (size_t)l * HIDDEN, Hout);
    }

    // V_out = segment_sum(H, src) ; H already in outH
    k_segsum<false><<<N_NODES, 64>>>(outH, rev, outV);
}